// round 10
// baseline (speedup 1.0000x reference)
#include <cuda_runtime.h>
#include <cuda_fp16.h>
#include <cstdint>

#define B_ 4
#define E_ 128
#define S_ 4096
#define BM 64
#define BN 64
#define NITER (S_ / BN)

// projected q,k,v in fp16, [b, s, e] row-major (q pre-scaled by 1/sqrt(E))
__device__ __align__(1024) __half g_q16[B_ * S_ * E_];
__device__ __align__(1024) __half g_k16[B_ * S_ * E_];
__device__ __align__(1024) __half g_v16[B_ * S_ * E_];

// ---------------------------------------------------------------------------
// helpers
// ---------------------------------------------------------------------------
__device__ __forceinline__ uint32_t smem_u32(const void* p) {
    uint32_t a;
    asm("{ .reg .u64 t; cvta.to.shared.u64 t, %1; cvt.u32.u64 %0, t; }" : "=r"(a) : "l"(p));
    return a;
}
__device__ __forceinline__ void mma_fp16(float* c, const uint32_t* a, uint32_t b0, uint32_t b1) {
    asm("mma.sync.aligned.m16n8k16.row.col.f32.f16.f16.f32 "
        "{%0,%1,%2,%3}, {%4,%5,%6,%7}, {%8,%9}, {%0,%1,%2,%3};"
        : "+f"(c[0]), "+f"(c[1]), "+f"(c[2]), "+f"(c[3])
        : "r"(a[0]), "r"(a[1]), "r"(a[2]), "r"(a[3]), "r"(b0), "r"(b1));
}
__device__ __forceinline__ void ldsm4(uint32_t* r, uint32_t a) {
    asm volatile("ldmatrix.sync.aligned.m8n8.x4.shared.b16 {%0,%1,%2,%3}, [%4];"
        : "=r"(r[0]), "=r"(r[1]), "=r"(r[2]), "=r"(r[3]) : "r"(a));
}
__device__ __forceinline__ void ldsm4t(uint32_t* r, uint32_t a) {
    asm volatile("ldmatrix.sync.aligned.m8n8.x4.trans.shared.b16 {%0,%1,%2,%3}, [%4];"
        : "=r"(r[0]), "=r"(r[1]), "=r"(r[2]), "=r"(r[3]) : "r"(a));
}
__device__ __forceinline__ uint32_t packh2(float x, float y) {
    uint32_t d;
    asm("cvt.rn.f16x2.f32 %0, %1, %2;" : "=r"(d) : "f"(y), "f"(x));
    return d;
}
__device__ __forceinline__ void cpa16(uint32_t dst, const void* src) {
    asm volatile("cp.async.cg.shared.global [%0], [%1], 16;" :: "r"(dst), "l"(src) : "memory");
}
__device__ __forceinline__ void sts1(uint32_t a, uint32_t v) {
    asm volatile("st.shared.b32 [%0], %1;" :: "r"(a), "r"(v) : "memory");
}
__device__ __forceinline__ void sts2(uint32_t a, uint32_t v0, uint32_t v1) {
    asm volatile("st.shared.v2.b32 [%0], {%1,%2};" :: "r"(a), "r"(v0), "r"(v1) : "memory");
}

#define ROWB 272   // 128 fp16 = 256B + 16B pad
#define PROWB 144  // 64 fp16 = 128B + 16B pad

// ---------------------------------------------------------------------------
// QKV projection via fp16 mma: one GEMM per CTA (which = blockIdx.z)
// ---------------------------------------------------------------------------
#define PX 0u
#define PW 34816u
#define PSMEM 69632

__global__ __launch_bounds__(256, 2) void qkv_proj_kernel(
    const float* __restrict__ x,
    const float* __restrict__ Wq, const float* __restrict__ bq,
    const float* __restrict__ Wk, const float* __restrict__ bk,
    const float* __restrict__ Wv, const float* __restrict__ bv) {
    extern __shared__ char smraw[];
    const uint32_t sb = smem_u32(smraw);

    const int tid  = threadIdx.x;
    const int lane = tid & 31;
    const int w    = tid >> 5;
    const int s0   = blockIdx.x * 128;
    const int b    = blockIdx.y;
    const int which = blockIdx.z;

    const float* W    = (which == 0) ? Wq : (which == 1) ? Wk : Wv;
    const float* bias = (which == 0) ? bq : (which == 1) ? bk : bv;
    __half* dst       = (which == 0) ? g_q16 : (which == 1) ? g_k16 : g_v16;
    const float oscale = (which == 0) ? 0.08838834764831845f : 1.0f;

    #pragma unroll
    for (int r = 0; r < 16; r++) {
        int f4 = r * 256 + tid;
        int i  = f4 >> 5;
        int sj = (f4 & 31) * 4;
        float4 v = *(const float4*)&x[(size_t)(b * E_ + i) * S_ + s0 + sj];
        sts2(sb + PX + (uint32_t)(i * ROWB + sj * 2),
             packh2(v.x, v.y), packh2(v.z, v.w));
        float4 u = *(const float4*)&W[(size_t)i * E_ + sj];
        sts2(sb + PW + (uint32_t)(i * ROWB + sj * 2),
             packh2(u.x, u.y), packh2(u.z, u.w));
    }
    __syncthreads();

    const int rowP = (lane & 7) + ((lane & 16) ? 8 : 0);
    const int colP = (lane & 8) ? 16 : 0;

    uint32_t xa[8][4];
    {
        const uint32_t ab = sb + PX + (uint32_t)(rowP * ROWB + w * 32 + colP);
        #pragma unroll
        for (int kg = 0; kg < 8; kg++)
            ldsm4t(xa[kg], ab + (uint32_t)(kg * 16 * ROWB));
    }

    float C[16][4];
    #pragma unroll
    for (int j = 0; j < 16; j++) {
        C[j][0] = 0.f; C[j][1] = 0.f; C[j][2] = 0.f; C[j][3] = 0.f;
    }

    const uint32_t kb = sb + PW + (uint32_t)(rowP * ROWB + colP);
    #pragma unroll
    for (int kg = 0; kg < 8; kg++) {
        #pragma unroll
        for (int nh = 0; nh < 2; nh++) {
            uint32_t bb[4][4];
            #pragma unroll
            for (int q = 0; q < 4; q++)
                ldsm4(bb[q], kb + (uint32_t)((nh * 4 + q) * 16 * ROWB + kg * 32));
            #pragma unroll
            for (int q = 0; q < 4; q++) {
                int j = (nh * 4 + q) * 2;
                mma_fp16(C[j],     xa[kg], bb[q][0], bb[q][1]);
                mma_fp16(C[j + 1], xa[kg], bb[q][2], bb[q][3]);
            }
        }
    }

    const int r0 = s0 + 16 * w + (lane >> 2);
    #pragma unroll
    for (int j = 0; j < 16; j++) {
        int eb = 8 * j + 2 * (lane & 3);
        float2 bb = *(const float2*)&bias[eb];
        uint32_t h0 = packh2((C[j][0] + bb.x) * oscale, (C[j][1] + bb.y) * oscale);
        uint32_t h1 = packh2((C[j][2] + bb.x) * oscale, (C[j][3] + bb.y) * oscale);
        size_t o0 = ((size_t)(b * S_) + r0) * E_ + eb;
        size_t o1 = o0 + 8 * E_;
        *(uint32_t*)&dst[o0] = h0;
        *(uint32_t*)&dst[o1] = h1;
    }
}

// ---------------------------------------------------------------------------
// flash attention: BM=64, 256 threads, 8 warps = 2m x 4n, 2 CTAs/SM
// QK: warp = m32 x n16 (K B-frag feeds 4 MMAs). PV: warp = m32 x e32.
// ONE __syncthreads per iter: P double-buffered, V triple-buffered.
// ---------------------------------------------------------------------------
#define KB  0u         // 2 x 17408
#define VB  34816u     // 3 x 17408 (slot 0 doubles as Q staging in prologue)
#define PT  87040u     // 2 x 9216
#define LPo 105472u    // 4 x 64 floats
#define ASMEM 106496

__device__ __forceinline__ void load_tile(uint32_t dstb, const __half* src,
                                          int b, int n0, int tid) {
    #pragma unroll
    for (int r = 0; r < 4; r++) {
        int idx = r * 256 + tid;
        int row = idx >> 4, ch = idx & 15;
        size_t g = ((size_t)(b * S_) + n0 + row) * E_ + ch * 8;
        cpa16(dstb + (uint32_t)(row * ROWB + ch * 16), src + g);
    }
}

// S = Q K^T : warp's m32 x n16 (kaddr pre-offset to warp's 16 n-rows)
// Sx[f]: f = mi*2 + nj  (mi = m16 half, nj = n8 half)
__device__ __forceinline__ void qk_block(float (*Sx)[4], const uint32_t (*qa)[2][4],
                                         uint32_t kaddr) {
    #pragma unroll
    for (int j = 0; j < 4; j++) {
        Sx[j][0] = 0.f; Sx[j][1] = 0.f; Sx[j][2] = 0.f; Sx[j][3] = 0.f;
    }
    #pragma unroll
    for (int d = 0; d < 8; d++) {
        uint32_t bb[4];
        ldsm4(bb, kaddr + (uint32_t)(d * 32));
        mma_fp16(Sx[0], qa[d][0], bb[0], bb[1]);
        mma_fp16(Sx[1], qa[d][0], bb[2], bb[3]);
        mma_fp16(Sx[2], qa[d][1], bb[0], bb[1]);
        mma_fp16(Sx[3], qa[d][1], bb[2], bb[3]);
    }
}

// O += P V : warp's m32 x e32 over k64.  O[mi*4 + ej]
__device__ __forceinline__ void pv_block(float (*O)[4], uint32_t pA, uint32_t vb) {
    #pragma unroll
    for (int kg = 0; kg < 4; kg++) {
        uint32_t p0[4], p1[4], v0[4], v1[4];
        ldsm4(p0, pA + (uint32_t)(kg * 32));
        ldsm4(p1, pA + (uint32_t)(16 * PROWB + kg * 32));
        ldsm4t(v0, vb + (uint32_t)(kg * 16 * ROWB));
        ldsm4t(v1, vb + (uint32_t)(kg * 16 * ROWB) + 32u);
        mma_fp16(O[0], p0, v0[0], v0[1]);
        mma_fp16(O[1], p0, v0[2], v0[3]);
        mma_fp16(O[2], p0, v1[0], v1[1]);
        mma_fp16(O[3], p0, v1[2], v1[3]);
        mma_fp16(O[4], p1, v0[0], v0[1]);
        mma_fp16(O[5], p1, v0[2], v0[3]);
        mma_fp16(O[6], p1, v1[0], v1[1]);
        mma_fp16(O[7], p1, v1[2], v1[3]);
    }
}

__global__ __launch_bounds__(256, 2) void attn_kernel(float* __restrict__ out) {
    extern __shared__ char smraw[];
    const uint32_t sb = smem_u32(smraw);

    const int tid  = threadIdx.x;
    const int lane = tid & 31;
    const int w    = tid >> 5;     // 0..7
    const int wq   = w & 3;        // n-quarter (QK) / e-quarter (PV)
    const int wm   = w >> 2;       // m-half (0..1), 32 rows each
    const int b    = blockIdx.y;
    const int m0   = blockIdx.x * BM;

    const int rowA = (lane & 7) + ((lane & 8) ? 8 : 0);     // A / trans-B pattern
    const int colA = (lane & 16) ? 16 : 0;
    const int rowK = (lane & 7) + ((lane & 16) ? 8 : 0);    // non-trans B pattern
    const int colK = (lane & 8) ? 16 : 0;

    const uint32_t koff  = (uint32_t)((16 * wq + rowK) * ROWB + colK);
    const uint32_t pAoff = (uint32_t)((32 * wm + rowA) * PROWB + colA);
    const uint32_t pWoff = (uint32_t)((32 * wm + (lane >> 2)) * PROWB
                                      + wq * 32 + (lane & 3) * 4);
    const uint32_t vwo   = (uint32_t)(rowA * ROWB + wq * 64 + colA);

    // ---- prologue: Q staged in VB slot 0, frags (m32) -> regs ----
    load_tile(sb + VB, g_q16, b, m0, tid);
    asm volatile("cp.async.commit_group;" ::: "memory");
    asm volatile("cp.async.wait_group 0;" ::: "memory");
    __syncthreads();

    uint32_t qa[8][2][4];
    {
        const uint32_t aaddr = sb + VB + (uint32_t)((32 * wm + rowA) * ROWB + colA);
        #pragma unroll
        for (int d = 0; d < 8; d++) {
            ldsm4(qa[d][0], aaddr + (uint32_t)(d * 32));
            ldsm4(qa[d][1], aaddr + (uint32_t)(16 * ROWB + d * 32));
        }
    }
    __syncthreads();   // Q reads done before V(0) overwrites

    load_tile(sb + KB,          g_k16, b, 0, tid);
    load_tile(sb + VB,          g_v16, b, 0, tid);
    load_tile(sb + KB + 17408u, g_k16, b, BN, tid);
    asm volatile("cp.async.commit_group;" ::: "memory");
    asm volatile("cp.async.wait_group 0;" ::: "memory");
    __syncthreads();

    float Sx[4][4];
    qk_block(Sx, qa, sb + KB + koff);

    float O[8][4];
    #pragma unroll
    for (int j = 0; j < 8; j++) {
        O[j][0] = 0.f; O[j][1] = 0.f; O[j][2] = 0.f; O[j][3] = 0.f;
    }
    float la[4] = {0.f, 0.f, 0.f, 0.f};   // [mi*2 + rowhalf]
    int vld = 1, vrd = 2;

    for (int it = 0; it < NITER; it++) {
        asm volatile("cp.async.wait_group 0;" ::: "memory");
        __syncthreads();

        if (it + 2 < NITER)
            load_tile(sb + KB + (uint32_t)(it & 1) * 17408u, g_k16, b, (it + 2) * BN, tid);
        if (it + 1 < NITER)
            load_tile(sb + VB + (uint32_t)vld * 17408u, g_v16, b, (it + 1) * BN, tid);
        asm volatile("cp.async.commit_group;" ::: "memory");

        // softmax(it) -> P buffer it&1
        {
            const uint32_t pWr = sb + PT + (uint32_t)(it & 1) * 9216u + pWoff;
            #pragma unroll
            for (int f = 0; f < 4; f++) {
                const int mi = f >> 1, nj = f & 1;
                float p0 = __expf(Sx[f][0]);
                float p1 = __expf(Sx[f][1]);
                float p2 = __expf(Sx[f][2]);
                float p3 = __expf(Sx[f][3]);
                la[mi * 2 + 0] += p0 + p1;
                la[mi * 2 + 1] += p2 + p3;
                const uint32_t a0 = pWr + (uint32_t)(mi * 16 * PROWB + nj * 16);
                sts1(a0,                        packh2(p0, p1));
                sts1(a0 + (uint32_t)(8 * PROWB), packh2(p2, p3));
            }
        }

        // PV(it-1)
        if (it > 0)
            pv_block(O, sb + PT + (uint32_t)((it - 1) & 1) * 9216u + pAoff,
                     sb + VB + (uint32_t)vrd * 17408u + vwo);

        // QK(it+1)
        if (it + 1 < NITER)
            qk_block(Sx, qa, sb + KB + (uint32_t)((it + 1) & 1) * 17408u + koff);

        vld = (vld == 2) ? 0 : vld + 1;
        vrd = (vrd == 2) ? 0 : vrd + 1;
    }

    // ---- epilogue: final PV, combine l across wq, store ----
    __syncthreads();
    pv_block(O, sb + PT + (uint32_t)((NITER - 1) & 1) * 9216u + pAoff,
             sb + VB + (uint32_t)vrd * 17408u + vwo);

    #pragma unroll
    for (int j = 0; j < 4; j++) {
        la[j] += __shfl_xor_sync(0xffffffffu, la[j], 1);
        la[j] += __shfl_xor_sync(0xffffffffu, la[j], 2);
    }

    float* LPf = (float*)(smraw + LPo);
    if ((lane & 3) == 0) {
        const int rl = 32 * wm + (lane >> 2);
        LPf[wq * 64 + rl]      = la[0];
        LPf[wq * 64 + rl + 8]  = la[1];
        LPf[wq * 64 + rl + 16] = la[2];
        LPf[wq * 64 + rl + 24] = la[3];
    }
    __syncthreads();

    #pragma unroll
    for (int mi = 0; mi < 2; mi++) {
        const int r0 = 32 * wm + 16 * mi + (lane >> 2);
        const float inv0 = 1.f / (LPf[r0] + LPf[64 + r0] + LPf[128 + r0] + LPf[192 + r0]);
        const float inv1 = 1.f / (LPf[r0 + 8] + LPf[64 + r0 + 8] + LPf[128 + r0 + 8] + LPf[192 + r0 + 8]);
        float* og0 = out + ((size_t)(b * S_) + m0 + r0) * E_;
        float* og8 = og0 + 8 * E_;
        #pragma unroll
        for (int ej = 0; ej < 4; ej++) {
            const int c = wq * 32 + ej * 8 + 2 * (lane & 3);
            const float* of = O[mi * 4 + ej];
            *(float2*)&og0[c] = make_float2(of[0] * inv0, of[1] * inv0);
            *(float2*)&og8[c] = make_float2(of[2] * inv1, of[3] * inv1);
        }
    }
}

// ---------------------------------------------------------------------------
extern "C" void kernel_launch(void* const* d_in, const int* in_sizes, int n_in,
                              void* d_out, int out_size) {
    const float* x  = (const float*)d_in[0];
    const float* Wq = (const float*)d_in[1];
    const float* bq = (const float*)d_in[2];
    const float* Wk = (const float*)d_in[3];
    const float* bk = (const float*)d_in[4];
    const float* Wv = (const float*)d_in[5];
    const float* bv = (const float*)d_in[6];
    float* out = (float*)d_out;

    {
        cudaFuncSetAttribute(qkv_proj_kernel,
                             cudaFuncAttributeMaxDynamicSharedMemorySize, PSMEM);
        dim3 grid(S_ / 128, B_, 3);
        qkv_proj_kernel<<<grid, 256, PSMEM>>>(x, Wq, bq, Wk, bk, Wv, bv);
    }
    {
        cudaFuncSetAttribute(attn_kernel,
                             cudaFuncAttributeMaxDynamicSharedMemorySize, ASMEM);
        dim3 grid(S_ / BM, B_);
        attn_kernel<<<grid, 256, ASMEM>>>(out);
    }
}

// round 11
// speedup vs baseline: 1.1046x; 1.1046x over previous
#include <cuda_runtime.h>
#include <cuda_fp16.h>
#include <cstdint>

#define B_ 4
#define E_ 128
#define S_ 4096
#define BM 64
#define BN 64
#define NITER (S_ / BN)

// projected q,k,v in fp16, [b, s, e] row-major (q pre-scaled by log2e/sqrt(E))
__device__ __align__(1024) __half g_q16[B_ * S_ * E_];
__device__ __align__(1024) __half g_k16[B_ * S_ * E_];
__device__ __align__(1024) __half g_v16[B_ * S_ * E_];

// ---------------------------------------------------------------------------
// helpers
// ---------------------------------------------------------------------------
__device__ __forceinline__ uint32_t smem_u32(const void* p) {
    uint32_t a;
    asm("{ .reg .u64 t; cvta.to.shared.u64 t, %1; cvt.u32.u64 %0, t; }" : "=r"(a) : "l"(p));
    return a;
}
__device__ __forceinline__ void mma_fp16(float* c, const uint32_t* a, uint32_t b0, uint32_t b1) {
    asm("mma.sync.aligned.m16n8k16.row.col.f32.f16.f16.f32 "
        "{%0,%1,%2,%3}, {%4,%5,%6,%7}, {%8,%9}, {%0,%1,%2,%3};"
        : "+f"(c[0]), "+f"(c[1]), "+f"(c[2]), "+f"(c[3])
        : "r"(a[0]), "r"(a[1]), "r"(a[2]), "r"(a[3]), "r"(b0), "r"(b1));
}
__device__ __forceinline__ void ldsm4(uint32_t* r, uint32_t a) {
    asm volatile("ldmatrix.sync.aligned.m8n8.x4.shared.b16 {%0,%1,%2,%3}, [%4];"
        : "=r"(r[0]), "=r"(r[1]), "=r"(r[2]), "=r"(r[3]) : "r"(a));
}
__device__ __forceinline__ void ldsm4t(uint32_t* r, uint32_t a) {
    asm volatile("ldmatrix.sync.aligned.m8n8.x4.trans.shared.b16 {%0,%1,%2,%3}, [%4];"
        : "=r"(r[0]), "=r"(r[1]), "=r"(r[2]), "=r"(r[3]) : "r"(a));
}
__device__ __forceinline__ uint32_t packh2(float x, float y) {
    uint32_t d;
    asm("cvt.rn.f16x2.f32 %0, %1, %2;" : "=r"(d) : "f"(y), "f"(x));
    return d;
}
__device__ __forceinline__ float ex2(float x) {
    float y;
    asm("ex2.approx.ftz.f32 %0, %1;" : "=f"(y) : "f"(x));
    return y;
}
__device__ __forceinline__ void cpa16(uint32_t dst, const void* src) {
    asm volatile("cp.async.cg.shared.global [%0], [%1], 16;" :: "r"(dst), "l"(src) : "memory");
}
__device__ __forceinline__ void sts1(uint32_t a, uint32_t v) {
    asm volatile("st.shared.b32 [%0], %1;" :: "r"(a), "r"(v) : "memory");
}
__device__ __forceinline__ void sts2(uint32_t a, uint32_t v0, uint32_t v1) {
    asm volatile("st.shared.v2.b32 [%0], {%1,%2};" :: "r"(a), "r"(v0), "r"(v1) : "memory");
}

#define ROWB 272   // 128 fp16 = 256B + 16B pad
#define PROWB 144  // 64 fp16 = 128B + 16B pad

// ---------------------------------------------------------------------------
// QKV projection via fp16 mma: one GEMM per CTA (which = blockIdx.z)
// q additionally scaled by log2(e)/sqrt(E) so softmax is a bare ex2
// ---------------------------------------------------------------------------
#define PX 0u
#define PW 34816u
#define PSMEM 69632

__global__ __launch_bounds__(256, 2) void qkv_proj_kernel(
    const float* __restrict__ x,
    const float* __restrict__ Wq, const float* __restrict__ bq,
    const float* __restrict__ Wk, const float* __restrict__ bk,
    const float* __restrict__ Wv, const float* __restrict__ bv) {
    extern __shared__ char smraw[];
    const uint32_t sb = smem_u32(smraw);

    const int tid  = threadIdx.x;
    const int lane = tid & 31;
    const int w    = tid >> 5;
    const int s0   = blockIdx.x * 128;
    const int b    = blockIdx.y;
    const int which = blockIdx.z;

    const float* W    = (which == 0) ? Wq : (which == 1) ? Wk : Wv;
    const float* bias = (which == 0) ? bq : (which == 1) ? bk : bv;
    __half* dst       = (which == 0) ? g_q16 : (which == 1) ? g_k16 : g_v16;
    const float oscale = (which == 0) ? 0.12751740f : 1.0f;   // log2e/sqrt(128)

    #pragma unroll
    for (int r = 0; r < 16; r++) {
        int f4 = r * 256 + tid;
        int i  = f4 >> 5;
        int sj = (f4 & 31) * 4;
        float4 v = *(const float4*)&x[(size_t)(b * E_ + i) * S_ + s0 + sj];
        sts2(sb + PX + (uint32_t)(i * ROWB + sj * 2),
             packh2(v.x, v.y), packh2(v.z, v.w));
        float4 u = *(const float4*)&W[(size_t)i * E_ + sj];
        sts2(sb + PW + (uint32_t)(i * ROWB + sj * 2),
             packh2(u.x, u.y), packh2(u.z, u.w));
    }
    __syncthreads();

    const int rowP = (lane & 7) + ((lane & 16) ? 8 : 0);
    const int colP = (lane & 8) ? 16 : 0;

    uint32_t xa[8][4];
    {
        const uint32_t ab = sb + PX + (uint32_t)(rowP * ROWB + w * 32 + colP);
        #pragma unroll
        for (int kg = 0; kg < 8; kg++)
            ldsm4t(xa[kg], ab + (uint32_t)(kg * 16 * ROWB));
    }

    float C[16][4];
    #pragma unroll
    for (int j = 0; j < 16; j++) {
        C[j][0] = 0.f; C[j][1] = 0.f; C[j][2] = 0.f; C[j][3] = 0.f;
    }

    const uint32_t kb = sb + PW + (uint32_t)(rowP * ROWB + colP);
    #pragma unroll
    for (int kg = 0; kg < 8; kg++) {
        #pragma unroll
        for (int nh = 0; nh < 2; nh++) {
            uint32_t bb[4][4];
            #pragma unroll
            for (int q = 0; q < 4; q++)
                ldsm4(bb[q], kb + (uint32_t)((nh * 4 + q) * 16 * ROWB + kg * 32));
            #pragma unroll
            for (int q = 0; q < 4; q++) {
                int j = (nh * 4 + q) * 2;
                mma_fp16(C[j],     xa[kg], bb[q][0], bb[q][1]);
                mma_fp16(C[j + 1], xa[kg], bb[q][2], bb[q][3]);
            }
        }
    }

    const int r0 = s0 + 16 * w + (lane >> 2);
    #pragma unroll
    for (int j = 0; j < 16; j++) {
        int eb = 8 * j + 2 * (lane & 3);
        float2 bb = *(const float2*)&bias[eb];
        uint32_t h0 = packh2((C[j][0] + bb.x) * oscale, (C[j][1] + bb.y) * oscale);
        uint32_t h1 = packh2((C[j][2] + bb.x) * oscale, (C[j][3] + bb.y) * oscale);
        size_t o0 = ((size_t)(b * S_) + r0) * E_ + eb;
        size_t o1 = o0 + 8 * E_;
        *(uint32_t*)&dst[o0] = h0;
        *(uint32_t*)&dst[o1] = h1;
    }
}

// ---------------------------------------------------------------------------
// flash attention (R8 structure): BM=64, 256 threads, 8 warps = 4m x 2n,
// 2 CTAs/SM.  QK: warp = m16 x n32.  P via smem.  PV: warp = m16 x e64.
// Two syncs/iter; K dist-2 / V dist-1 double buffers.
// ---------------------------------------------------------------------------
#define KB0 0u
#define KB1 17408u
#define VB0 34816u
#define VB1 52224u
#define QT  69632u
#define PT  87040u     // 64 x 144B = 9216
#define LPo 96256u     // 128 floats
#define ASMEM 96768

__device__ __forceinline__ void load_tile(uint32_t dstb, const __half* src,
                                          int b, int n0, int tid) {
    #pragma unroll
    for (int r = 0; r < 4; r++) {
        int idx = r * 256 + tid;
        int row = idx >> 4, ch = idx & 15;
        size_t g = ((size_t)(b * S_) + n0 + row) * E_ + ch * 8;
        cpa16(dstb + (uint32_t)(row * ROWB + ch * 16), src + g);
    }
}

// S = Q K^T : warp's m16 x n32 (kaddr pre-offset to warp's n-rows)
__device__ __forceinline__ void qk_block(float (*Sx)[4], const uint32_t (*qa)[4],
                                         uint32_t kaddr) {
    #pragma unroll
    for (int j = 0; j < 4; j++) {
        Sx[j][0] = 0.f; Sx[j][1] = 0.f; Sx[j][2] = 0.f; Sx[j][3] = 0.f;
    }
    #pragma unroll
    for (int d = 0; d < 8; d++) {
        uint32_t bb[2][4];
        ldsm4(bb[0], kaddr + (uint32_t)(d * 32));
        ldsm4(bb[1], kaddr + (uint32_t)(16 * ROWB + d * 32));
        mma_fp16(Sx[0], qa[d], bb[0][0], bb[0][1]);
        mma_fp16(Sx[1], qa[d], bb[0][2], bb[0][3]);
        mma_fp16(Sx[2], qa[d], bb[1][0], bb[1][1]);
        mma_fp16(Sx[3], qa[d], bb[1][2], bb[1][3]);
    }
}

__global__ __launch_bounds__(256, 2) void attn_kernel(float* __restrict__ out) {
    extern __shared__ char smraw[];
    const uint32_t sb = smem_u32(smraw);

    const int tid  = threadIdx.x;
    const int lane = tid & 31;
    const int w    = tid >> 5;     // 0..7
    const int wn   = w & 1;        // n-half / e-half
    const int wm   = w >> 1;       // m-group 0..3
    const int b    = blockIdx.y;
    const int m0   = blockIdx.x * BM;

    const int rowA = (lane & 7) + ((lane & 8) ? 8 : 0);     // A / trans-B
    const int colA = (lane & 16) ? 16 : 0;
    const int rowK = (lane & 7) + ((lane & 16) ? 8 : 0);    // non-trans B
    const int colK = (lane & 8) ? 16 : 0;

    const uint32_t koff = (uint32_t)((32 * wn + rowK) * ROWB + colK);
    const uint32_t pA   = sb + PT + (uint32_t)((16 * wm + rowA) * PROWB + colA);
    const uint32_t pWr  = sb + PT + (uint32_t)((16 * wm + (lane >> 2)) * PROWB
                                               + wn * 64 + (lane & 3) * 4);
    const uint32_t vwo  = (uint32_t)(rowA * ROWB + colA + wn * 128);

    load_tile(sb + QT,  g_q16, b, m0, tid);
    load_tile(sb + KB0, g_k16, b, 0, tid);
    load_tile(sb + VB0, g_v16, b, 0, tid);
    asm volatile("cp.async.commit_group;" ::: "memory");
    load_tile(sb + KB1, g_k16, b, BN, tid);
    asm volatile("cp.async.commit_group;" ::: "memory");
    asm volatile("cp.async.wait_group 1;" ::: "memory");
    __syncthreads();

    // Q frags -> registers (persistent)
    uint32_t qa[8][4];
    {
        const uint32_t aaddr = sb + QT + (uint32_t)((16 * wm + rowA) * ROWB + colA);
        #pragma unroll
        for (int d = 0; d < 8; d++)
            ldsm4(qa[d], aaddr + (uint32_t)(d * 32));
    }

    float Sx[4][4];
    qk_block(Sx, qa, sb + KB0 + koff);

    float O[8][4];
    #pragma unroll
    for (int j = 0; j < 8; j++) {
        O[j][0] = 0.f; O[j][1] = 0.f; O[j][2] = 0.f; O[j][3] = 0.f;
    }
    float lacc0 = 0.f, lacc1 = 0.f;

    for (int it = 0; it < NITER; it++) {
        asm volatile("cp.async.wait_group 0;" ::: "memory");
        __syncthreads();   // K/V ready; PV(it-1) P-reads complete

        if (it + 2 < NITER)
            load_tile(sb + ((it & 1) ? KB1 : KB0), g_k16, b, (it + 2) * BN, tid);
        if (it + 1 < NITER)
            load_tile(sb + (((it + 1) & 1) ? VB1 : VB0), g_v16, b, (it + 1) * BN, tid);
        asm volatile("cp.async.commit_group;" ::: "memory");

        // softmax(it) + store P to smem (q pre-scaled by log2e/sqrt(E))
        #pragma unroll
        for (int j = 0; j < 4; j++) {
            float p0 = ex2(Sx[j][0]);
            float p1 = ex2(Sx[j][1]);
            float p2 = ex2(Sx[j][2]);
            float p3 = ex2(Sx[j][3]);
            lacc0 += p0 + p1;
            lacc1 += p2 + p3;
            sts1(pWr + (uint32_t)(j * 16),             packh2(p0, p1));
            sts1(pWr + (uint32_t)(j * 16 + 8 * PROWB), packh2(p2, p3));
        }
        __syncthreads();   // P visible

        // QK(it+1)
        if (it + 1 < NITER)
            qk_block(Sx, qa, sb + (((it + 1) & 1) ? KB1 : KB0) + koff);

        // PV(it): A = P[m16, k64] from smem, B = V[k64, e64] (warp's e-half)
        {
            const uint32_t vb = sb + ((it & 1) ? VB1 : VB0) + vwo;
            #pragma unroll
            for (int kg = 0; kg < 4; kg++) {
                uint32_t pa4[4];
                ldsm4(pa4, pA + (uint32_t)(kg * 32));
                uint32_t v4[4][4];
                #pragma unroll
                for (int q = 0; q < 4; q++)
                    ldsm4t(v4[q], vb + (uint32_t)(kg * 16 * ROWB + q * 32));
                #pragma unroll
                for (int q = 0; q < 4; q++) {
                    mma_fp16(O[q * 2],     pa4, v4[q][0], v4[q][1]);
                    mma_fp16(O[q * 2 + 1], pa4, v4[q][2], v4[q][3]);
                }
            }
        }
    }

    // ---- epilogue ----
    lacc0 += __shfl_xor_sync(0xffffffffu, lacc0, 1);
    lacc0 += __shfl_xor_sync(0xffffffffu, lacc0, 2);
    lacc1 += __shfl_xor_sync(0xffffffffu, lacc1, 1);
    lacc1 += __shfl_xor_sync(0xffffffffu, lacc1, 2);

    float* LPf = (float*)(smraw + LPo);
    if ((lane & 3) == 0) {
        LPf[wn * 64 + wm * 16 + (lane >> 2)]     = lacc0;
        LPf[wn * 64 + wm * 16 + (lane >> 2) + 8] = lacc1;
    }
    __syncthreads();

    const int rloc = wm * 16 + (lane >> 2);
    const float inv0 = 1.f / (LPf[rloc]     + LPf[64 + rloc]);
    const float inv1 = 1.f / (LPf[rloc + 8] + LPf[64 + rloc + 8]);

    const int r0 = m0 + rloc;
    const int c0 = wn * 64 + 2 * (lane & 3);
    float* o0 = out + ((size_t)(b * S_) + r0) * E_;
    float* o8 = o0 + 8 * E_;
    #pragma unroll
    for (int j = 0; j < 8; j++) {
        *(float2*)&o0[8 * j + c0] = make_float2(O[j][0] * inv0, O[j][1] * inv0);
        *(float2*)&o8[8 * j + c0] = make_float2(O[j][2] * inv1, O[j][3] * inv1);
    }
}

// ---------------------------------------------------------------------------
extern "C" void kernel_launch(void* const* d_in, const int* in_sizes, int n_in,
                              void* d_out, int out_size) {
    const float* x  = (const float*)d_in[0];
    const float* Wq = (const float*)d_in[1];
    const float* bq = (const float*)d_in[2];
    const float* Wk = (const float*)d_in[3];
    const float* bk = (const float*)d_in[4];
    const float* Wv = (const float*)d_in[5];
    const float* bv = (const float*)d_in[6];
    float* out = (float*)d_out;

    {
        cudaFuncSetAttribute(qkv_proj_kernel,
                             cudaFuncAttributeMaxDynamicSharedMemorySize, PSMEM);
        dim3 grid(S_ / 128, B_, 3);
        qkv_proj_kernel<<<grid, 256, PSMEM>>>(x, Wq, bq, Wk, bk, Wv, bv);
    }
    {
        cudaFuncSetAttribute(attn_kernel,
                             cudaFuncAttributeMaxDynamicSharedMemorySize, ASMEM);
        dim3 grid(S_ / BM, B_);
        attn_kernel<<<grid, 256, ASMEM>>>(out);
    }
}